// round 16
// baseline (speedup 1.0000x reference)
#include <cuda_runtime.h>
#include <cuda_fp16.h>
#include <math.h>
#include <stdint.h>

#define B_   64
#define N_   36
#define ROWS 2304      // B_*N_
#define DF   2048
#define DATT 512

// packed chunk sizes
#define PA_W 3072      // fp16 A: 128 rows x 24 words
#define PB_W 4160      // fp16 W: 16 word-rows x 260
#define PR_CH 1440     // fp32 relattn operands: 36 x 40 floats

// ---------------- scratch ----------------------------------------------------
__device__ float    g_tmp1[ROWS * DF];     // qe@Wq, then unrounded fused
__device__ float    g_tmp2[ROWS * DF];     // obj@Wo
__device__ float    g_ra[ROWS * DF];       // natural outputs
__device__ float    g_rb[ROWS * DF];
__device__ float    g_ba[ROWS * DF];
__device__ float    g_bb[ROWS * DF];
__device__ uint32_t g_pqe[18 * 64 * PA_W];    // packed fp16 A operands
__device__ uint32_t g_pobj[18 * 64 * PA_W];
__device__ uint32_t g_pfus[18 * 64 * PA_W];
__device__ uint32_t g_pWq[8 * 64 * PB_W];     // packed fp16 weights
__device__ uint32_t g_pWo[8 * 64 * PB_W];
__device__ uint32_t g_pWfa[8 * 64 * PB_W];
__device__ uint32_t g_pWfb[8 * 64 * PB_W];
__device__ uint32_t g_pW0h[2 * 64 * PB_W];    // packed fp16 W0 (relattn)
__device__ float    g_pra[B_ * 64 * PR_CH];   // packed raw fp32 relattn operands
__device__ float    g_prb[B_ * 64 * PR_CH];
__device__ float    g_pba[B_ * 64 * PR_CH];
__device__ float    g_pbb[B_ * 64 * PR_CH];
__device__ float    g_scp[2 * 9 * B_ * 144];

// ---------------- PTX helpers ------------------------------------------------
__device__ __forceinline__ uint32_t smem_u32(const void* p) {
    uint32_t a;
    asm("{ .reg .u64 t; cvta.to.shared.u64 t, %1; cvt.u32.u64 %0, t; }" : "=r"(a) : "l"(p));
    return a;
}
__device__ __forceinline__ uint32_t packh2(float x, float y) {
    __half2 h = __floats2half2_rn(x, y);
    return *(uint32_t*)&h;
}
__device__ __forceinline__ void mma16(float* d, const uint32_t* a, const uint32_t* b) {
    asm volatile("mma.sync.aligned.m16n8k16.row.col.f32.f16.f16.f32 "
                 "{%0,%1,%2,%3}, {%4,%5,%6,%7}, {%8,%9}, {%0,%1,%2,%3};"
                 : "+f"(d[0]), "+f"(d[1]), "+f"(d[2]), "+f"(d[3])
                 : "r"(a[0]), "r"(a[1]), "r"(a[2]), "r"(a[3]),
                   "r"(b[0]), "r"(b[1]));
}
__device__ __forceinline__ void blkcp(uint32_t dst, const void* src,
                                      uint32_t bytes, uint32_t bar) {
    asm volatile("cp.async.bulk.shared::cta.global.mbarrier::complete_tx::bytes "
                 "[%0], [%1], %2, [%3];"
                 :: "r"(dst), "l"(src), "r"(bytes), "r"(bar) : "memory");
}
#define MBAR_INIT(a, n) \
    asm volatile("mbarrier.init.shared.b64 [%0], %1;" :: "r"(a), "r"(n) : "memory")
#define MBAR_EXPECT(a, n) \
    asm volatile("mbarrier.arrive.expect_tx.shared.b64 _, [%0], %1;" :: "r"(a), "r"(n) : "memory")
#define MBAR_WAIT(a, ph) do {                                                   \
    uint32_t _m = (a), _p = (ph), _d;                                           \
    asm volatile("{\n\t.reg .pred p;\n\t"                                       \
        "mbarrier.try_wait.parity.acquire.cta.shared::cta.b64 p, [%1], %2;\n\t" \
        "selp.b32 %0, 1, 0, p;\n\t}" : "=r"(_d) : "r"(_m), "r"(_p) : "memory"); \
    if (!_d) {                                                                  \
        asm volatile("{\n\t.reg .pred P;\n\t"                                   \
            "WL_%=:\n\t"                                                        \
            "mbarrier.try_wait.parity.acquire.cta.shared::cta.b64 P, [%0], %1, 0x989680;\n\t" \
            "@P bra.uni WD_%=;\n\t"                                             \
            "bra.uni WL_%=;\n\t"                                                \
            "WD_%=:\n\t}" :: "r"(_m), "r"(_p) : "memory");                      \
    } } while (0)

// k-word permutation within a K=16 block (8 half2 words):
// logical w -> phys (w<4 ? 2w : 2(w-4)+1): fragment pairs adjacent -> LDS.64
__device__ __forceinline__ int kperm(int wl) {
    int blk = wl >> 3, wi = wl & 7;
    return blk * 8 + ((wi < 4) ? 2 * wi : 2 * (wi - 4) + 1);
}

// ---------------- packing / elementwise kernels ------------------------------
// All 5 weight packs in one launch. z<4: [2048][2048]; z=4: W0 [2048][512].
__global__ void packWall(const float* __restrict__ Wq, const float* __restrict__ Wo,
                         const float* __restrict__ Wfa, const float* __restrict__ Wfb,
                         const float* __restrict__ W0,
                         uint32_t* __restrict__ pWq, uint32_t* __restrict__ pWo,
                         uint32_t* __restrict__ pWfa, uint32_t* __restrict__ pWfb,
                         uint32_t* __restrict__ pW0h) {
    int z = blockIdx.z;
    const float* in;
    uint32_t* out;
    int ncols;
    switch (z) {
        case 0: in = Wq;  out = pWq;  ncols = DF;   break;
        case 1: in = Wo;  out = pWo;  ncols = DF;   break;
        case 2: in = Wfa; out = pWfa; ncols = DF;   break;
        case 3: in = Wfb; out = pWfb; ncols = DF;   break;
        default: in = W0; out = pW0h; ncols = DATT; break;
    }
    int i = blockIdx.x * blockDim.x + threadIdx.x;
    int nq = ncols / 4;
    if (i >= (DF / 2) * nq) return;
    int n4 = (i % nq) * 4;
    int kk = (i / nq) * 2;
    float4 a = *(const float4*)&in[(size_t)kk * ncols + n4];
    float4 b = *(const float4*)&in[(size_t)(kk + 1) * ncols + n4];
    uint4 w;
    w.x = packh2(a.x, b.x); w.y = packh2(a.y, b.y);
    w.z = packh2(a.z, b.z); w.w = packh2(a.w, b.w);
    int p = kperm((kk & 31) >> 1);
    size_t o = ((size_t)((n4 >> 8) * 64 + (kk >> 5)) * 16 + p) * 260 + (n4 & 255);
    *(uint4*)&out[o] = w;
}

// A packs (qe, obj) in one launch: grid (4608, 1, 2)
__global__ void packAh2(const float* __restrict__ qe, const float* __restrict__ obj,
                        uint32_t* __restrict__ pqe, uint32_t* __restrict__ pobj) {
    const float* in  = blockIdx.z ? obj : qe;
    uint32_t* out    = blockIdx.z ? pobj : pqe;
    int i = blockIdx.x * blockDim.x + threadIdx.x;
    if (i >= ROWS * DF / 4) return;
    int e = i * 4;
    int r = e / DF, c = e % DF;
    float4 v = *(const float4*)&in[e];
    uint32_t h0 = packh2(v.x, v.y), h1 = packh2(v.z, v.w);
    size_t rowb = ((size_t)((r >> 7) * 64 + (c >> 5)) * 128 + (r & 127)) * 24;
    int wl = (c & 31) >> 1;
    out[rowb + kperm(wl)]     = h0;
    out[rowb + kperm(wl + 1)] = h1;
}

// tmp1 = tmp1*tmp2 (natural fp32, residual); packed fp16 product -> pfus
__global__ void fusekh(float* __restrict__ a, const float* __restrict__ b,
                       uint32_t* __restrict__ pk) {
    int i = blockIdx.x * blockDim.x + threadIdx.x;
    if (i >= ROWS * DF / 4) return;
    int e = i * 4;
    int r = e / DF, c = e % DF;
    float4 x = *(float4*)&a[e];
    float4 y = *(const float4*)&b[e];
    x.x *= y.x; x.y *= y.y; x.z *= y.z; x.w *= y.w;
    *(float4*)&a[e] = x;
    uint32_t h0 = packh2(x.x, x.y), h1 = packh2(x.z, x.w);
    size_t rowb = ((size_t)((r >> 7) * 64 + (c >> 5)) * 128 + (r & 127)) * 24;
    int wl = (c & 31) >> 1;
    pk[rowb + kperm(wl)]     = h0;
    pk[rowb + kperm(wl + 1)] = h1;
}

// ba/bb natural + packed relattn layout, from boxes (K = 4)
__global__ void boxproj(const float* __restrict__ boxes,
                        const float* __restrict__ Wba, const float* __restrict__ Wbb,
                        float* __restrict__ ba, float* __restrict__ bb,
                        float* __restrict__ pba, float* __restrict__ pbb) {
    int idx = blockIdx.x * blockDim.x + threadIdx.x;
    if (idx >= ROWS * (DF / 4)) return;
    int r  = idx / (DF / 4);
    int dq = (idx % (DF / 4)) * 4;
    float4 bx = *(const float4*)&boxes[r * 4];
    float c[4] = {bx.x, bx.y, bx.z, bx.w};
    float4 sa = make_float4(0.f, 0.f, 0.f, 0.f);
    float4 sb = make_float4(0.f, 0.f, 0.f, 0.f);
#pragma unroll
    for (int cc = 0; cc < 4; cc++) {
        float4 wa = *(const float4*)&Wba[cc * DF + dq];
        float4 wb = *(const float4*)&Wbb[cc * DF + dq];
        sa.x += c[cc] * wa.x; sa.y += c[cc] * wa.y; sa.z += c[cc] * wa.z; sa.w += c[cc] * wa.w;
        sb.x += c[cc] * wb.x; sb.y += c[cc] * wb.y; sb.z += c[cc] * wb.z; sb.w += c[cc] * wb.w;
    }
    *(float4*)&ba[(size_t)r * DF + dq] = sa;
    *(float4*)&bb[(size_t)r * DF + dq] = sb;
    int b = r / N_, j = r - b * N_;
    size_t o = ((size_t)(b * 64 + (dq >> 5)) * 36 + j) * 40 + (dq & 31);
    *(float4*)&pba[o] = sa;
    *(float4*)&pbb[o] = sb;
}

// ---------------------------------------------------------------------------
// Dual fp16 mma.sync GEMM (fp32 acc): grid (8, 18, 2), z selects operand set.
// CTA 128x256, 3 stages, K-chunk 32 (2 x K16), 8 warps of 64x64.
// ---------------------------------------------------------------------------
#define G_SMEM ((16 + 3 * PA_W + 3 * PB_W) * 4)
__global__ __launch_bounds__(256)
void gemm_hz(const uint32_t* __restrict__ pa0, const uint32_t* __restrict__ pb0,
             float* __restrict__ C0, float* __restrict__ Cp0,
             const uint32_t* __restrict__ pa1, const uint32_t* __restrict__ pb1,
             float* __restrict__ C1, float* __restrict__ Cp1) {
    const uint32_t* pa = blockIdx.z ? pa1 : pa0;
    const uint32_t* pb = blockIdx.z ? pb1 : pb0;
    float* C  = blockIdx.z ? C1 : C0;
    float* Cp = blockIdx.z ? Cp1 : Cp0;

    extern __shared__ uint32_t smw[];
    uint32_t smb = smem_u32(smw);
    const int tid = threadIdx.x, lane = tid & 31, wid = tid >> 5;
    const int cc = lane & 3, q = lane >> 2;
    const int wm = (wid >> 2) * 64, wn = (wid & 3) * 64;
    const int tileM = blockIdx.y, tileN = blockIdx.x;
    const uint32_t* As = smw + 16;
    const uint32_t* Bs = smw + 16 + 3 * PA_W;

    if (tid == 0) {
#pragma unroll
        for (int s = 0; s < 3; s++) MBAR_INIT(smb + 8 * s, 1);
    }
    __syncthreads();

    auto issue = [&](int kc) {
        int s = kc % 3;
        uint32_t bar = smb + 8 * s;
        MBAR_EXPECT(bar, 28928);
        blkcp(smb + (16 + s * PA_W) * 4,
              pa + ((size_t)tileM * 64 + kc) * PA_W, 12288, bar);
        blkcp(smb + (16 + 3 * PA_W + s * PB_W) * 4,
              pb + ((size_t)tileN * 64 + kc) * PB_W, 16640, bar);
    };
    if (tid == 0) { issue(0); issue(1); issue(2); }

    float acc[4][8][4];
#pragma unroll
    for (int i = 0; i < 4; i++)
#pragma unroll
        for (int j = 0; j < 8; j++)
#pragma unroll
            for (int p = 0; p < 4; p++) acc[i][j][p] = 0.f;

    for (int kc = 0; kc < 64; kc++) {
        int s = kc % 3;
        MBAR_WAIT(smb + 8 * s, (kc / 3) & 1);
        const uint32_t* Ab = As + s * PA_W;
        const uint32_t* Bb = Bs + s * PB_W;
#pragma unroll
        for (int kb = 0; kb < 2; kb++) {
            uint32_t af[4][4], bf[8][2];
#pragma unroll
            for (int mf = 0; mf < 4; mf++) {
                int r = wm + mf * 16 + q;
                uint2 lo = *(const uint2*)&Ab[r * 24 + kb * 8 + 2 * cc];
                uint2 hi = *(const uint2*)&Ab[(r + 8) * 24 + kb * 8 + 2 * cc];
                af[mf][0] = lo.x; af[mf][1] = hi.x;
                af[mf][2] = lo.y; af[mf][3] = hi.y;
            }
#pragma unroll
            for (int nf = 0; nf < 8; nf++) {
                int n = wn + nf * 8 + q;
                bf[nf][0] = Bb[(kb * 8 + 2 * cc) * 260 + n];
                bf[nf][1] = Bb[(kb * 8 + 2 * cc + 1) * 260 + n];
            }
#pragma unroll
            for (int mf = 0; mf < 4; mf++)
#pragma unroll
                for (int nf = 0; nf < 8; nf++)
                    mma16(acc[mf][nf], af[mf], bf[nf]);
        }
        __syncthreads();
        if (tid == 0 && kc + 3 < 64) issue(kc + 3);
    }

    const int m0 = tileM * 128, n0 = tileN * 256;
#pragma unroll
    for (int mf = 0; mf < 4; mf++) {
        int r0 = m0 + wm + mf * 16 + q;
#pragma unroll
        for (int nf = 0; nf < 8; nf++) {
            int c = n0 + wn + nf * 8 + 2 * cc;
            float2 v0 = make_float2(acc[mf][nf][0], acc[mf][nf][1]);
            float2 v1 = make_float2(acc[mf][nf][2], acc[mf][nf][3]);
            *(float2*)&C[(size_t)r0 * DF + c] = v0;
            *(float2*)&C[(size_t)(r0 + 8) * DF + c] = v1;
            if (Cp) {
                int b0i = r0 / 36, j0 = r0 - b0i * 36;
                int b1i = (r0 + 8) / 36, j1 = (r0 + 8) - b1i * 36;
                size_t o0 = ((size_t)(b0i * 64 + (c >> 5)) * 36 + j0) * 40 + (c & 31);
                size_t o1 = ((size_t)(b1i * 64 + (c >> 5)) * 36 + j1) * 40 + (c & 31);
                *(float2*)&Cp[o0] = v0;
                *(float2*)&Cp[o1] = v1;
            }
        }
    }
}

// ---------------------------------------------------------------------------
// Relation-attention scores: fp16 mma, 4-stage operand ring, interleaved
// G-build (tensor-bubble fill):
//   prologue: issue 0,1,2,3; wait(0); buildG(0)
//   loop kc:  sync; [kc>=1] issue(kc+3);
//             mma kb=0 (G[kc], Ws[kc%4]);
//             wait(kc+1); buildG_half0(kc+1);
//             mma kb=1;
//             buildG_half1(kc+1)
// Slot safety: at iter kc, slot (kc+3)%4 = (kc-1)%4 fully consumed before
// this iteration's sync (mma(kc-1), buildG(kc-1)).
// smem words: bars 0..31, Ws@32 (4x4160), rbS@16672 (4x1440), bbS@22432,
//   raS@28192 (4x160), baS@28832, Gs@29472 (2x3456), red@36384. 36960 words.
// ---------------------------------------------------------------------------
#define R_SMEM (36960 * 4)
__global__ __launch_bounds__(384)
void relattn_h5(const float* __restrict__ pra, const float* __restrict__ prb,
                const float* __restrict__ pba, const float* __restrict__ pbb,
                const uint32_t* __restrict__ pw0, const float* __restrict__ b0,
                const float* __restrict__ W1, float* __restrict__ scp) {
    extern __shared__ uint32_t smw[];
    float* smf = (float*)smw;
    uint32_t smb = smem_u32(smw);
    const uint32_t* Ws = smw + 32;
    const float* rbS = smf + 16672;
    const float* bbS = smf + 22432;
    const float* raS = smf + 28192;
    const float* baS = smf + 28832;
    uint32_t* Gs = smw + 29472;
    float* red = smf + 36384;
    const int tid = threadIdx.x, lane = tid & 31, wid = tid >> 5;
    const int cc = lane & 3, q = lane >> 2;
    const int wm = (wid >> 2) * 48, wn = (wid & 3) * 64;
    const int slice = blockIdx.x, ig = blockIdx.y, b = blockIdx.z;

    if (tid == 0) {
#pragma unroll
        for (int s = 0; s < 4; s++) MBAR_INIT(smb + 8 * s, 1);
    }
    __syncthreads();

    auto issue = [&](int kc) {
        int s = kc & 3;
        uint32_t bar = smb + 8 * s;
        MBAR_EXPECT(bar, 29440);
        blkcp(smb + (32 + s * PB_W) * 4,
              pw0 + ((size_t)slice * 64 + kc) * PB_W, 16640, bar);
        size_t rbase = ((size_t)b * 64 + kc) * PR_CH;
        blkcp(smb + (16672 + s * PR_CH) * 4, prb + rbase, 5760, bar);
        blkcp(smb + (22432 + s * PR_CH) * 4, pbb + rbase, 5760, bar);
        blkcp(smb + (28192 + s * 160) * 4, pra + rbase + ig * 160, 640, bar);
        blkcp(smb + (28832 + s * 160) * 4, pba + rbase + ig * 160, 640, bar);
    };
    auto buildG_half = [&](int kc, int h) {
        int s = kc & 3;
        const float* rs = rbS + s * PR_CH;
        const float* bs = bbS + s * PR_CH;
        const float* us = raS + s * 160;
        const float* vs = baS + s * 160;
        uint32_t* Gw = Gs + (kc & 1) * 3456;
#pragma unroll
        for (int p = 3 * h; p < 3 * h + 3; p++) {
            int idx = tid + 384 * p;       // < 2304
            int r = idx >> 4, wl = idx & 15;
            int il = r / 36, j = r - il * 36;
            int k = 2 * wl;
            float2 rv = *(const float2*)&rs[j * 40 + k];
            float2 bv = *(const float2*)&bs[j * 40 + k];
            float2 u  = *(const float2*)&us[il * 40 + k];
            float2 v  = *(const float2*)&vs[il * 40 + k];
            float g0 = fmaf(v.x, bv.x, u.x * rv.x);
            float g1 = fmaf(v.y, bv.y, u.y * rv.y);
            Gw[r * 24 + kperm(wl)] = packh2(g0, g1);
        }
    };

    if (tid == 0) { issue(0); issue(1); issue(2); issue(3); }

    float acc[3][8][4];
#pragma unroll
    for (int i = 0; i < 3; i++)
#pragma unroll
        for (int j = 0; j < 8; j++)
#pragma unroll
            for (int p = 0; p < 4; p++) acc[i][j][p] = 0.f;

    MBAR_WAIT(smb + 0, 0);
    buildG_half(0, 0);
    buildG_half(0, 1);

    for (int kc = 0; kc < 64; kc++) {
        int s = kc & 3;
        __syncthreads();   // G[kc] visible; slot (kc-1)%4 consumers all done
        if (tid == 0 && kc >= 1 && kc + 3 < 64) issue(kc + 3);
        const uint32_t* Wb = Ws + s * PB_W;
        const uint32_t* Gw = Gs + (kc & 1) * 3456;
        // ---- kb = 0 ----
        {
            uint32_t af[3][4], bf[8][2];
#pragma unroll
            for (int mf = 0; mf < 3; mf++) {
                int r = wm + mf * 16 + q;
                uint2 lo = *(const uint2*)&Gw[r * 24 + 2 * cc];
                uint2 hi = *(const uint2*)&Gw[(r + 8) * 24 + 2 * cc];
                af[mf][0] = lo.x; af[mf][1] = hi.x;
                af[mf][2] = lo.y; af[mf][3] = hi.y;
            }
#pragma unroll
            for (int nf = 0; nf < 8; nf++) {
                int n = wn + nf * 8 + q;
                bf[nf][0] = Wb[(2 * cc) * 260 + n];
                bf[nf][1] = Wb[(2 * cc + 1) * 260 + n];
            }
#pragma unroll
            for (int mf = 0; mf < 3; mf++)
#pragma unroll
                for (int nf = 0; nf < 8; nf++)
                    mma16(acc[mf][nf], af[mf], bf[nf]);
        }
        // fill tensor-drain window: wait + first half of next G build
        if (kc + 1 < 64) {
            MBAR_WAIT(smb + 8 * ((kc + 1) & 3), ((kc + 1) >> 2) & 1);
            buildG_half(kc + 1, 0);
        }
        // ---- kb = 1 ----
        {
            uint32_t af[3][4], bf[8][2];
#pragma unroll
            for (int mf = 0; mf < 3; mf++) {
                int r = wm + mf * 16 + q;
                uint2 lo = *(const uint2*)&Gw[r * 24 + 8 + 2 * cc];
                uint2 hi = *(const uint2*)&Gw[(r + 8) * 24 + 8 + 2 * cc];
                af[mf][0] = lo.x; af[mf][1] = hi.x;
                af[mf][2] = lo.y; af[mf][3] = hi.y;
            }
#pragma unroll
            for (int nf = 0; nf < 8; nf++) {
                int n = wn + nf * 8 + q;
                bf[nf][0] = Wb[(8 + 2 * cc) * 260 + n];
                bf[nf][1] = Wb[(8 + 2 * cc + 1) * 260 + n];
            }
#pragma unroll
            for (int mf = 0; mf < 3; mf++)
#pragma unroll
                for (int nf = 0; nf < 8; nf++)
                    mma16(acc[mf][nf], af[mf], bf[nf]);
        }
        if (kc + 1 < 64) buildG_half(kc + 1, 1);
    }
    __syncthreads();

    // epilogue: partial scores over this 256-col slice (deterministic order)
    const float* b0g = b0 + slice * 256;
    const float* W1g = W1 + slice * 256;
#pragma unroll
    for (int mf = 0; mf < 3; mf++) {
        float s0 = 0.f, s1 = 0.f;
#pragma unroll
        for (int nf = 0; nf < 8; nf++) {
            int c0 = wn + nf * 8 + 2 * cc;
            float w0 = W1g[c0],     e0 = b0g[c0];
            float w1 = W1g[c0 + 1], e1 = b0g[c0 + 1];
            s0 += w0 * tanhf(acc[mf][nf][0] + e0) + w1 * tanhf(acc[mf][nf][1] + e1);
            s1 += w0 * tanhf(acc[mf][nf][2] + e0) + w1 * tanhf(acc[mf][nf][3] + e1);
        }
        s0 += __shfl_xor_sync(0xffffffffu, s0, 1);
        s0 += __shfl_xor_sync(0xffffffffu, s0, 2);
        s1 += __shfl_xor_sync(0xffffffffu, s1, 1);
        s1 += __shfl_xor_sync(0xffffffffu, s1, 2);
        if (cc == 0) {
            int r = wm + mf * 16 + q;
            red[r * 4 + (wid & 3)]       = s0;
            red[(r + 8) * 4 + (wid & 3)] = s1;
        }
    }
    __syncthreads();
    if (tid < 144) {
        float tot = red[tid * 4] + red[tid * 4 + 1] + red[tid * 4 + 2] + red[tid * 4 + 3];
        scp[(((size_t)slice * B_ + b) * 9 + ig) * 144 + tid] = tot;
    }
}

// out = obj + fused + ra.*(att@rb) + ba.*(att@bb); softmax computed in-block.
__global__ __launch_bounds__(256)
void ehat_fin2(const float* __restrict__ scp,
               const float* __restrict__ ra, const float* __restrict__ rb,
               const float* __restrict__ ba, const float* __restrict__ bb,
               const float* __restrict__ obj, const float* __restrict__ fus,
               float* __restrict__ out) {
    __shared__ float att_s[N_][N_ + 1];
    const int tid = threadIdx.x;
    const int b = blockIdx.y, d0 = blockIdx.x * 128;
    const int d = tid & 127, half = tid >> 7;
    for (int idx = tid; idx < N_ * N_; idx += 256) {
        int i = idx / N_, j = idx % N_;
        int ig = i >> 2, il = i & 3;
        float s = scp[(((size_t)b) * 9 + ig) * 144 + il * 36 + j]
                + scp[(((size_t)B_ + b) * 9 + ig) * 144 + il * 36 + j];
        att_s[i][j] = s;
    }
    __syncthreads();
    if (tid < N_) {       // per-i softmax, serial = deterministic
        float m = att_s[tid][0];
#pragma unroll 4
        for (int j = 1; j < N_; j++) m = fmaxf(m, att_s[tid][j]);
        float sum = 0.f;
#pragma unroll 4
        for (int j = 0; j < N_; j++) {
            float e = expf(att_s[tid][j] - m);
            att_s[tid][j] = e;
            sum += e;
        }
        float inv = 1.f / sum;
#pragma unroll 4
        for (int j = 0; j < N_; j++) att_s[tid][j] *= inv;
    }
    __syncthreads();
    const float* rbB = rb + (size_t)b * N_ * DF + d0 + d;
    const float* bbB = bb + (size_t)b * N_ * DF + d0 + d;
    float accR[18], accB[18];
#pragma unroll
    for (int i = 0; i < 18; i++) { accR[i] = 0.f; accB[i] = 0.f; }
    for (int j = 0; j < N_; j++) {
        float rv = rbB[(size_t)j * DF];
        float bv = bbB[(size_t)j * DF];
#pragma unroll
        for (int i = 0; i < 18; i++) {
            float a = att_s[half * 18 + i][j];
            accR[i] += a * rv;
            accB[i] += a * bv;
        }
    }
#pragma unroll
    for (int i = 0; i < 18; i++) {
        size_t row = (size_t)b * N_ + half * 18 + i;
        size_t off = row * DF + d0 + d;
        out[off] = obj[off] + fus[off] + ra[off] * accR[i] + ba[off] * accB[i];
    }
}

extern "C" void kernel_launch(void* const* d_in, const int* in_sizes, int n_in,
                              void* d_out, int out_size) {
    const float* qe    = (const float*)d_in[0];
    const float* obj   = (const float*)d_in[1];
    const float* boxes = (const float*)d_in[2];
    const float* Wq    = (const float*)d_in[3];
    const float* Wo    = (const float*)d_in[4];
    const float* Wfa   = (const float*)d_in[5];
    const float* Wfb   = (const float*)d_in[6];
    const float* Wba   = (const float*)d_in[7];
    const float* Wbb   = (const float*)d_in[8];
    const float* W0    = (const float*)d_in[9];
    const float* b0    = (const float*)d_in[10];
    const float* W1    = (const float*)d_in[11];
    float* out = (float*)d_out;

    float *tmp1, *tmp2, *ra, *rb, *ba, *bb;
    float *pra, *prb, *pba, *pbb, *scp;
    uint32_t *pqe, *pobj, *pfus, *pWq, *pWo, *pWfa, *pWfb, *pW0h;
    cudaGetSymbolAddress((void**)&tmp1, g_tmp1);
    cudaGetSymbolAddress((void**)&tmp2, g_tmp2);
    cudaGetSymbolAddress((void**)&ra,   g_ra);
    cudaGetSymbolAddress((void**)&rb,   g_rb);
    cudaGetSymbolAddress((void**)&ba,   g_ba);
    cudaGetSymbolAddress((void**)&bb,   g_bb);
    cudaGetSymbolAddress((void**)&pqe,  g_pqe);
    cudaGetSymbolAddress((void**)&pobj, g_pobj);
    cudaGetSymbolAddress((void**)&pfus, g_pfus);
    cudaGetSymbolAddress((void**)&pWq,  g_pWq);
    cudaGetSymbolAddress((void**)&pWo,  g_pWo);
    cudaGetSymbolAddress((void**)&pWfa, g_pWfa);
    cudaGetSymbolAddress((void**)&pWfb, g_pWfb);
    cudaGetSymbolAddress((void**)&pW0h, g_pW0h);
    cudaGetSymbolAddress((void**)&pra,  g_pra);
    cudaGetSymbolAddress((void**)&prb,  g_prb);
    cudaGetSymbolAddress((void**)&pba,  g_pba);
    cudaGetSymbolAddress((void**)&pbb,  g_pbb);
    cudaGetSymbolAddress((void**)&scp,  g_scp);

    cudaFuncSetAttribute(gemm_hz, cudaFuncAttributeMaxDynamicSharedMemorySize, G_SMEM);
    cudaFuncSetAttribute(relattn_h5, cudaFuncAttributeMaxDynamicSharedMemorySize, R_SMEM);

    const int nIO = ROWS * DF / 4;           // 1179648

    dim3 gg(DF / 256, ROWS / 128, 2);        // (8, 18, 2)

    boxproj<<<(nIO + 255) / 256, 256>>>(boxes, Wba, Wbb, ba, bb, pba, pbb);   // 1
    packWall<<<dim3(2048, 1, 5), 256>>>(Wq, Wo, Wfa, Wfb, W0,
                                        pWq, pWo, pWfa, pWfb, pW0h);          // 2
    packAh2<<<dim3(4608, 1, 2), 256>>>(qe, obj, pqe, pobj);                   // 3
    gemm_hz<<<gg, 256, G_SMEM>>>(pqe, pWq, tmp1, nullptr,
                                 pobj, pWo, tmp2, nullptr);                   // 4
    fusekh<<<(nIO + 255) / 256, 256>>>(tmp1, tmp2, pfus);                     // 5
    gemm_hz<<<gg, 256, G_SMEM>>>(pfus, pWfa, ra, pra,
                                 pfus, pWfb, rb, prb);                        // 6 (profiled)
    relattn_h5<<<dim3(2, 9, B_), 384, R_SMEM>>>(pra, prb, pba, pbb,
                                                pW0h, b0, W1, scp);           // 7
    ehat_fin2<<<dim3(16, B_), 256>>>(scp, ra, rb, ba, bb, obj, tmp1, out);    // 8
}

// round 17
// speedup vs baseline: 1.0334x; 1.0334x over previous
#include <cuda_runtime.h>
#include <cuda_fp16.h>
#include <math.h>
#include <stdint.h>

#define B_   64
#define N_   36
#define ROWS 2304      // B_*N_
#define DF   2048
#define DATT 512

// packed chunk sizes (per 32-k chunk)
#define PA_W 3072      // fp16 A: 128 rows x 24 words
#define PB_W 4160      // fp16 W: 16 word-rows x 260
#define PR_CH 1440     // fp32 relattn operands: 36 x 40 floats
// gemm stages are 64-k (two contiguous 32-k chunks)
#define PA2_W (2 * PA_W)
#define PB2_W (2 * PB_W)

// ---------------- scratch ----------------------------------------------------
__device__ float    g_tmp1[ROWS * DF];     // qe@Wq, then unrounded fused
__device__ float    g_tmp2[ROWS * DF];     // obj@Wo
__device__ float    g_ra[ROWS * DF];       // natural outputs
__device__ float    g_rb[ROWS * DF];
__device__ float    g_ba[ROWS * DF];
__device__ float    g_bb[ROWS * DF];
__device__ uint32_t g_pqe[18 * 64 * PA_W];    // packed fp16 A operands
__device__ uint32_t g_pobj[18 * 64 * PA_W];
__device__ uint32_t g_pfus[18 * 64 * PA_W];
__device__ uint32_t g_pWq[8 * 64 * PB_W];     // packed fp16 weights
__device__ uint32_t g_pWo[8 * 64 * PB_W];
__device__ uint32_t g_pWfa[8 * 64 * PB_W];
__device__ uint32_t g_pWfb[8 * 64 * PB_W];
__device__ uint32_t g_pW0h[2 * 64 * PB_W];    // packed fp16 W0 (relattn)
__device__ float    g_pra[B_ * 64 * PR_CH];   // packed raw fp32 relattn operands
__device__ float    g_prb[B_ * 64 * PR_CH];
__device__ float    g_pba[B_ * 64 * PR_CH];
__device__ float    g_pbb[B_ * 64 * PR_CH];
__device__ float    g_scp[2 * 9 * B_ * 144];

// ---------------- PTX helpers ------------------------------------------------
__device__ __forceinline__ uint32_t smem_u32(const void* p) {
    uint32_t a;
    asm("{ .reg .u64 t; cvta.to.shared.u64 t, %1; cvt.u32.u64 %0, t; }" : "=r"(a) : "l"(p));
    return a;
}
__device__ __forceinline__ uint32_t packh2(float x, float y) {
    __half2 h = __floats2half2_rn(x, y);
    return *(uint32_t*)&h;
}
__device__ __forceinline__ void mma16(float* d, const uint32_t* a, const uint32_t* b) {
    asm volatile("mma.sync.aligned.m16n8k16.row.col.f32.f16.f16.f32 "
                 "{%0,%1,%2,%3}, {%4,%5,%6,%7}, {%8,%9}, {%0,%1,%2,%3};"
                 : "+f"(d[0]), "+f"(d[1]), "+f"(d[2]), "+f"(d[3])
                 : "r"(a[0]), "r"(a[1]), "r"(a[2]), "r"(a[3]),
                   "r"(b[0]), "r"(b[1]));
}
__device__ __forceinline__ void blkcp(uint32_t dst, const void* src,
                                      uint32_t bytes, uint32_t bar) {
    asm volatile("cp.async.bulk.shared::cta.global.mbarrier::complete_tx::bytes "
                 "[%0], [%1], %2, [%3];"
                 :: "r"(dst), "l"(src), "r"(bytes), "r"(bar) : "memory");
}
#define MBAR_INIT(a, n) \
    asm volatile("mbarrier.init.shared.b64 [%0], %1;" :: "r"(a), "r"(n) : "memory")
#define MBAR_EXPECT(a, n) \
    asm volatile("mbarrier.arrive.expect_tx.shared.b64 _, [%0], %1;" :: "r"(a), "r"(n) : "memory")
#define MBAR_WAIT(a, ph) do {                                                   \
    uint32_t _m = (a), _p = (ph), _d;                                           \
    asm volatile("{\n\t.reg .pred p;\n\t"                                       \
        "mbarrier.try_wait.parity.acquire.cta.shared::cta.b64 p, [%1], %2;\n\t" \
        "selp.b32 %0, 1, 0, p;\n\t}" : "=r"(_d) : "r"(_m), "r"(_p) : "memory"); \
    if (!_d) {                                                                  \
        asm volatile("{\n\t.reg .pred P;\n\t"                                   \
            "WL_%=:\n\t"                                                        \
            "mbarrier.try_wait.parity.acquire.cta.shared::cta.b64 P, [%0], %1, 0x989680;\n\t" \
            "@P bra.uni WD_%=;\n\t"                                             \
            "bra.uni WL_%=;\n\t"                                                \
            "WD_%=:\n\t}" :: "r"(_m), "r"(_p) : "memory");                      \
    } } while (0)

// k-word permutation within a K=16 block (8 half2 words):
// logical w -> phys (w<4 ? 2w : 2(w-4)+1): fragment pairs adjacent -> LDS.64
__device__ __forceinline__ int kperm(int wl) {
    int blk = wl >> 3, wi = wl & 7;
    return blk * 8 + ((wi < 4) ? 2 * wi : 2 * (wi - 4) + 1);
}

// ---------------- packing / elementwise kernels ------------------------------
// All 5 weight packs in one launch. z<4: [2048][2048]; z=4: W0 [2048][512].
__global__ void packWall(const float* __restrict__ Wq, const float* __restrict__ Wo,
                         const float* __restrict__ Wfa, const float* __restrict__ Wfb,
                         const float* __restrict__ W0,
                         uint32_t* __restrict__ pWq, uint32_t* __restrict__ pWo,
                         uint32_t* __restrict__ pWfa, uint32_t* __restrict__ pWfb,
                         uint32_t* __restrict__ pW0h) {
    int z = blockIdx.z;
    const float* in;
    uint32_t* out;
    int ncols;
    switch (z) {
        case 0: in = Wq;  out = pWq;  ncols = DF;   break;
        case 1: in = Wo;  out = pWo;  ncols = DF;   break;
        case 2: in = Wfa; out = pWfa; ncols = DF;   break;
        case 3: in = Wfb; out = pWfb; ncols = DF;   break;
        default: in = W0; out = pW0h; ncols = DATT; break;
    }
    int i = blockIdx.x * blockDim.x + threadIdx.x;
    int nq = ncols / 4;
    if (i >= (DF / 2) * nq) return;
    int n4 = (i % nq) * 4;
    int kk = (i / nq) * 2;
    float4 a = *(const float4*)&in[(size_t)kk * ncols + n4];
    float4 b = *(const float4*)&in[(size_t)(kk + 1) * ncols + n4];
    uint4 w;
    w.x = packh2(a.x, b.x); w.y = packh2(a.y, b.y);
    w.z = packh2(a.z, b.z); w.w = packh2(a.w, b.w);
    int p = kperm((kk & 31) >> 1);
    size_t o = ((size_t)((n4 >> 8) * 64 + (kk >> 5)) * 16 + p) * 260 + (n4 & 255);
    *(uint4*)&out[o] = w;
}

// A packs (qe, obj) in one launch: grid (4608, 1, 2)
__global__ void packAh2(const float* __restrict__ qe, const float* __restrict__ obj,
                        uint32_t* __restrict__ pqe, uint32_t* __restrict__ pobj) {
    const float* in  = blockIdx.z ? obj : qe;
    uint32_t* out    = blockIdx.z ? pobj : pqe;
    int i = blockIdx.x * blockDim.x + threadIdx.x;
    if (i >= ROWS * DF / 4) return;
    int e = i * 4;
    int r = e / DF, c = e % DF;
    float4 v = *(const float4*)&in[e];
    uint32_t h0 = packh2(v.x, v.y), h1 = packh2(v.z, v.w);
    size_t rowb = ((size_t)((r >> 7) * 64 + (c >> 5)) * 128 + (r & 127)) * 24;
    int wl = (c & 31) >> 1;
    out[rowb + kperm(wl)]     = h0;
    out[rowb + kperm(wl + 1)] = h1;
}

// tmp1 = tmp1*tmp2 (natural fp32, residual); packed fp16 product -> pfus
__global__ void fusekh(float* __restrict__ a, const float* __restrict__ b,
                       uint32_t* __restrict__ pk) {
    int i = blockIdx.x * blockDim.x + threadIdx.x;
    if (i >= ROWS * DF / 4) return;
    int e = i * 4;
    int r = e / DF, c = e % DF;
    float4 x = *(float4*)&a[e];
    float4 y = *(const float4*)&b[e];
    x.x *= y.x; x.y *= y.y; x.z *= y.z; x.w *= y.w;
    *(float4*)&a[e] = x;
    uint32_t h0 = packh2(x.x, x.y), h1 = packh2(x.z, x.w);
    size_t rowb = ((size_t)((r >> 7) * 64 + (c >> 5)) * 128 + (r & 127)) * 24;
    int wl = (c & 31) >> 1;
    pk[rowb + kperm(wl)]     = h0;
    pk[rowb + kperm(wl + 1)] = h1;
}

// ba/bb natural + packed relattn layout, from boxes (K = 4)
__global__ void boxproj(const float* __restrict__ boxes,
                        const float* __restrict__ Wba, const float* __restrict__ Wbb,
                        float* __restrict__ ba, float* __restrict__ bb,
                        float* __restrict__ pba, float* __restrict__ pbb) {
    int idx = blockIdx.x * blockDim.x + threadIdx.x;
    if (idx >= ROWS * (DF / 4)) return;
    int r  = idx / (DF / 4);
    int dq = (idx % (DF / 4)) * 4;
    float4 bx = *(const float4*)&boxes[r * 4];
    float c[4] = {bx.x, bx.y, bx.z, bx.w};
    float4 sa = make_float4(0.f, 0.f, 0.f, 0.f);
    float4 sb = make_float4(0.f, 0.f, 0.f, 0.f);
#pragma unroll
    for (int cc = 0; cc < 4; cc++) {
        float4 wa = *(const float4*)&Wba[cc * DF + dq];
        float4 wb = *(const float4*)&Wbb[cc * DF + dq];
        sa.x += c[cc] * wa.x; sa.y += c[cc] * wa.y; sa.z += c[cc] * wa.z; sa.w += c[cc] * wa.w;
        sb.x += c[cc] * wb.x; sb.y += c[cc] * wb.y; sb.z += c[cc] * wb.z; sb.w += c[cc] * wb.w;
    }
    *(float4*)&ba[(size_t)r * DF + dq] = sa;
    *(float4*)&bb[(size_t)r * DF + dq] = sb;
    int b = r / N_, j = r - b * N_;
    size_t o = ((size_t)(b * 64 + (dq >> 5)) * 36 + j) * 40 + (dq & 31);
    *(float4*)&pba[o] = sa;
    *(float4*)&pbb[o] = sb;
}

// ---------------------------------------------------------------------------
// Dual fp16 mma.sync GEMM (fp32 acc): grid (8, 18, 2), z selects operand set.
// CTA 128x256, 3 stages of K-chunk 64 (two contiguous packed 32-k chunks),
// 32 iterations, 8 warps of 64x64. Halves barrier/wait count vs K32.
// ---------------------------------------------------------------------------
#define G_SMEM ((16 + 3 * PA2_W + 3 * PB2_W) * 4)
__global__ __launch_bounds__(256)
void gemm_hz(const uint32_t* __restrict__ pa0, const uint32_t* __restrict__ pb0,
             float* __restrict__ C0, float* __restrict__ Cp0,
             const uint32_t* __restrict__ pa1, const uint32_t* __restrict__ pb1,
             float* __restrict__ C1, float* __restrict__ Cp1) {
    const uint32_t* pa = blockIdx.z ? pa1 : pa0;
    const uint32_t* pb = blockIdx.z ? pb1 : pb0;
    float* C  = blockIdx.z ? C1 : C0;
    float* Cp = blockIdx.z ? Cp1 : Cp0;

    extern __shared__ uint32_t smw[];
    uint32_t smb = smem_u32(smw);
    const int tid = threadIdx.x, lane = tid & 31, wid = tid >> 5;
    const int cc = lane & 3, q = lane >> 2;
    const int wm = (wid >> 2) * 64, wn = (wid & 3) * 64;
    const int tileM = blockIdx.y, tileN = blockIdx.x;
    const uint32_t* As = smw + 16;
    const uint32_t* Bs = smw + 16 + 3 * PA2_W;

    if (tid == 0) {
#pragma unroll
        for (int s = 0; s < 3; s++) MBAR_INIT(smb + 8 * s, 1);
    }
    __syncthreads();

    auto issue = [&](int c64) {       // c64 in [0, 32)
        int s = c64 % 3;
        uint32_t bar = smb + 8 * s;
        MBAR_EXPECT(bar, 57856);
        blkcp(smb + (16 + s * PA2_W) * 4,
              pa + ((size_t)tileM * 64 + c64 * 2) * PA_W, 24576, bar);
        blkcp(smb + (16 + 3 * PA2_W + s * PB2_W) * 4,
              pb + ((size_t)tileN * 64 + c64 * 2) * PB_W, 33280, bar);
    };
    if (tid == 0) { issue(0); issue(1); issue(2); }

    float acc[4][8][4];
#pragma unroll
    for (int i = 0; i < 4; i++)
#pragma unroll
        for (int j = 0; j < 8; j++)
#pragma unroll
            for (int p = 0; p < 4; p++) acc[i][j][p] = 0.f;

    for (int c64 = 0; c64 < 32; c64++) {
        int s = c64 % 3;
        MBAR_WAIT(smb + 8 * s, (c64 / 3) & 1);
        const uint32_t* Ab = As + s * PA2_W;
        const uint32_t* Bb = Bs + s * PB2_W;
#pragma unroll
        for (int kbi = 0; kbi < 4; kbi++) {      // 4 x K16 per 64-k stage
            const int sub = kbi >> 1, kb = kbi & 1;
            const uint32_t* Asub = Ab + sub * PA_W;
            const uint32_t* Bsub = Bb + sub * PB_W;
            uint32_t af[4][4], bf[8][2];
#pragma unroll
            for (int mf = 0; mf < 4; mf++) {
                int r = wm + mf * 16 + q;
                uint2 lo = *(const uint2*)&Asub[r * 24 + kb * 8 + 2 * cc];
                uint2 hi = *(const uint2*)&Asub[(r + 8) * 24 + kb * 8 + 2 * cc];
                af[mf][0] = lo.x; af[mf][1] = hi.x;
                af[mf][2] = lo.y; af[mf][3] = hi.y;
            }
#pragma unroll
            for (int nf = 0; nf < 8; nf++) {
                int n = wn + nf * 8 + q;
                bf[nf][0] = Bsub[(kb * 8 + 2 * cc) * 260 + n];
                bf[nf][1] = Bsub[(kb * 8 + 2 * cc + 1) * 260 + n];
            }
#pragma unroll
            for (int mf = 0; mf < 4; mf++)
#pragma unroll
                for (int nf = 0; nf < 8; nf++)
                    mma16(acc[mf][nf], af[mf], bf[nf]);
        }
        __syncthreads();
        if (tid == 0 && c64 + 3 < 32) issue(c64 + 3);
    }

    const int m0 = tileM * 128, n0 = tileN * 256;
#pragma unroll
    for (int mf = 0; mf < 4; mf++) {
        int r0 = m0 + wm + mf * 16 + q;
#pragma unroll
        for (int nf = 0; nf < 8; nf++) {
            int c = n0 + wn + nf * 8 + 2 * cc;
            float2 v0 = make_float2(acc[mf][nf][0], acc[mf][nf][1]);
            float2 v1 = make_float2(acc[mf][nf][2], acc[mf][nf][3]);
            *(float2*)&C[(size_t)r0 * DF + c] = v0;
            *(float2*)&C[(size_t)(r0 + 8) * DF + c] = v1;
            if (Cp) {
                int b0i = r0 / 36, j0 = r0 - b0i * 36;
                int b1i = (r0 + 8) / 36, j1 = (r0 + 8) - b1i * 36;
                size_t o0 = ((size_t)(b0i * 64 + (c >> 5)) * 36 + j0) * 40 + (c & 31);
                size_t o1 = ((size_t)(b1i * 64 + (c >> 5)) * 36 + j1) * 40 + (c & 31);
                *(float2*)&Cp[o0] = v0;
                *(float2*)&Cp[o1] = v1;
            }
        }
    }
}

// ---------------------------------------------------------------------------
// Relation-attention scores (round-15 proven version): fp16 mma + smem
// G-build, single sync per chunk, THREE-stage operand buffers:
//   prologue: issue 0,1,2; wait(0); buildG(0)
//   loop kc:  sync; [kc>=1] issue(kc+2); mma(G[kc] w/ Ws[kc%3]);
//             wait((kc+1)%3); buildG(kc+1)
// smem words: bars 0..15, Ws@16 (3x4160), rbS@12496 (3x1440), bbS@16816,
//   raS@21136 (3x160), baS@21616, Gs@22096 (2x3456), red@29008. 29584 words.
// ---------------------------------------------------------------------------
#define R_SMEM (29584 * 4)
__global__ __launch_bounds__(384)
void relattn_h4(const float* __restrict__ pra, const float* __restrict__ prb,
                const float* __restrict__ pba, const float* __restrict__ pbb,
                const uint32_t* __restrict__ pw0, const float* __restrict__ b0,
                const float* __restrict__ W1, float* __restrict__ scp) {
    extern __shared__ uint32_t smw[];
    float* smf = (float*)smw;
    uint32_t smb = smem_u32(smw);
    const uint32_t* Ws = smw + 16;
    const float* rbS = smf + 12496;
    const float* bbS = smf + 16816;
    const float* raS = smf + 21136;
    const float* baS = smf + 21616;
    uint32_t* Gs = smw + 22096;
    float* red = smf + 29008;
    const int tid = threadIdx.x, lane = tid & 31, wid = tid >> 5;
    const int cc = lane & 3, q = lane >> 2;
    const int wm = (wid >> 2) * 48, wn = (wid & 3) * 64;
    const int slice = blockIdx.x, ig = blockIdx.y, b = blockIdx.z;

    if (tid == 0) {
#pragma unroll
        for (int s = 0; s < 3; s++) MBAR_INIT(smb + 8 * s, 1);
    }
    __syncthreads();

    auto issue = [&](int kc) {
        int s = kc % 3;
        uint32_t bar = smb + 8 * s;
        MBAR_EXPECT(bar, 29440);
        blkcp(smb + (16 + s * PB_W) * 4,
              pw0 + ((size_t)slice * 64 + kc) * PB_W, 16640, bar);
        size_t rbase = ((size_t)b * 64 + kc) * PR_CH;
        blkcp(smb + (12496 + s * PR_CH) * 4, prb + rbase, 5760, bar);
        blkcp(smb + (16816 + s * PR_CH) * 4, pbb + rbase, 5760, bar);
        blkcp(smb + (21136 + s * 160) * 4, pra + rbase + ig * 160, 640, bar);
        blkcp(smb + (21616 + s * 160) * 4, pba + rbase + ig * 160, 640, bar);
    };
    auto buildG = [&](int kc) {
        int s = kc % 3;
        const float* rs = rbS + s * PR_CH;
        const float* bs = bbS + s * PR_CH;
        const float* us = raS + s * 160;
        const float* vs = baS + s * 160;
        uint32_t* Gw = Gs + (kc & 1) * 3456;
#pragma unroll
        for (int p = 0; p < 6; p++) {
            int idx = tid + 384 * p;       // < 2304
            int r = idx >> 4, wl = idx & 15;
            int il = r / 36, j = r - il * 36;
            int k = 2 * wl;
            float2 rv = *(const float2*)&rs[j * 40 + k];
            float2 bv = *(const float2*)&bs[j * 40 + k];
            float2 u  = *(const float2*)&us[il * 40 + k];
            float2 v  = *(const float2*)&vs[il * 40 + k];
            float g0 = fmaf(v.x, bv.x, u.x * rv.x);
            float g1 = fmaf(v.y, bv.y, u.y * rv.y);
            Gw[r * 24 + kperm(wl)] = packh2(g0, g1);
        }
    };

    if (tid == 0) { issue(0); issue(1); issue(2); }

    float acc[3][8][4];
#pragma unroll
    for (int i = 0; i < 3; i++)
#pragma unroll
        for (int j = 0; j < 8; j++)
#pragma unroll
            for (int p = 0; p < 4; p++) acc[i][j][p] = 0.f;

    MBAR_WAIT(smb + 0, 0);
    buildG(0);

    for (int kc = 0; kc < 64; kc++) {
        int s = kc % 3;
        __syncthreads();   // G[kc] visible; mma reads of slot (kc-1)%3 all done
        if (tid == 0 && kc >= 1 && kc + 2 < 64) issue(kc + 2);
        const uint32_t* Wb = Ws + s * PB_W;
        const uint32_t* Gw = Gs + (kc & 1) * 3456;
#pragma unroll
        for (int kb = 0; kb < 2; kb++) {
            uint32_t af[3][4], bf[8][2];
#pragma unroll
            for (int mf = 0; mf < 3; mf++) {
                int r = wm + mf * 16 + q;
                uint2 lo = *(const uint2*)&Gw[r * 24 + kb * 8 + 2 * cc];
                uint2 hi = *(const uint2*)&Gw[(r + 8) * 24 + kb * 8 + 2 * cc];
                af[mf][0] = lo.x; af[mf][1] = hi.x;
                af[mf][2] = lo.y; af[mf][3] = hi.y;
            }
#pragma unroll
            for (int nf = 0; nf < 8; nf++) {
                int n = wn + nf * 8 + q;
                bf[nf][0] = Wb[(kb * 8 + 2 * cc) * 260 + n];
                bf[nf][1] = Wb[(kb * 8 + 2 * cc + 1) * 260 + n];
            }
#pragma unroll
            for (int mf = 0; mf < 3; mf++)
#pragma unroll
                for (int nf = 0; nf < 8; nf++)
                    mma16(acc[mf][nf], af[mf], bf[nf]);
        }
        if (kc + 1 < 64) {
            MBAR_WAIT(smb + 8 * ((kc + 1) % 3), ((kc + 1) / 3) & 1);
            buildG(kc + 1);
        }
    }
    __syncthreads();

    // epilogue: partial scores over this 256-col slice (deterministic order)
    const float* b0g = b0 + slice * 256;
    const float* W1g = W1 + slice * 256;
#pragma unroll
    for (int mf = 0; mf < 3; mf++) {
        float s0 = 0.f, s1 = 0.f;
#pragma unroll
        for (int nf = 0; nf < 8; nf++) {
            int c0 = wn + nf * 8 + 2 * cc;
            float w0 = W1g[c0],     e0 = b0g[c0];
            float w1 = W1g[c0 + 1], e1 = b0g[c0 + 1];
            s0 += w0 * tanhf(acc[mf][nf][0] + e0) + w1 * tanhf(acc[mf][nf][1] + e1);
            s1 += w0 * tanhf(acc[mf][nf][2] + e0) + w1 * tanhf(acc[mf][nf][3] + e1);
        }
        s0 += __shfl_xor_sync(0xffffffffu, s0, 1);
        s0 += __shfl_xor_sync(0xffffffffu, s0, 2);
        s1 += __shfl_xor_sync(0xffffffffu, s1, 1);
        s1 += __shfl_xor_sync(0xffffffffu, s1, 2);
        if (cc == 0) {
            int r = wm + mf * 16 + q;
            red[r * 4 + (wid & 3)]       = s0;
            red[(r + 8) * 4 + (wid & 3)] = s1;
        }
    }
    __syncthreads();
    if (tid < 144) {
        float tot = red[tid * 4] + red[tid * 4 + 1] + red[tid * 4 + 2] + red[tid * 4 + 3];
        scp[(((size_t)slice * B_ + b) * 9 + ig) * 144 + tid] = tot;
    }
}

// out = obj + fused + ra.*(att@rb) + ba.*(att@bb); softmax computed in-block.
__global__ __launch_bounds__(256)
void ehat_fin2(const float* __restrict__ scp,
               const float* __restrict__ ra, const float* __restrict__ rb,
               const float* __restrict__ ba, const float* __restrict__ bb,
               const float* __restrict__ obj, const float* __restrict__ fus,
               float* __restrict__ out) {
    __shared__ float att_s[N_][N_ + 1];
    const int tid = threadIdx.x;
    const int b = blockIdx.y, d0 = blockIdx.x * 128;
    const int d = tid & 127, half = tid >> 7;
    for (int idx = tid; idx < N_ * N_; idx += 256) {
        int i = idx / N_, j = idx % N_;
        int ig = i >> 2, il = i & 3;
        float s = scp[(((size_t)b) * 9 + ig) * 144 + il * 36 + j]
                + scp[(((size_t)B_ + b) * 9 + ig) * 144 + il * 36 + j];
        att_s[i][j] = s;
    }
    __syncthreads();
    if (tid < N_) {       // per-i softmax, serial = deterministic
        float m = att_s[tid][0];
#pragma unroll 4
        for (int j = 1; j < N_; j++) m = fmaxf(m, att_s[tid][j]);
        float sum = 0.f;
#pragma unroll 4
        for (int j = 0; j < N_; j++) {
            float e = expf(att_s[tid][j] - m);
            att_s[tid][j] = e;
            sum += e;
        }
        float inv = 1.f / sum;
#pragma unroll 4
        for (int j = 0; j < N_; j++) att_s[tid][j] *= inv;
    }
    __syncthreads();
    const float* rbB = rb + (size_t)b * N_ * DF + d0 + d;
    const float* bbB = bb + (size_t)b * N_ * DF + d0 + d;
    float accR[18], accB[18];
#pragma unroll
    for (int i = 0; i < 18; i++) { accR[i] = 0.f; accB[i] = 0.f; }
    for (int j = 0; j < N_; j++) {
        float rv = rbB[(size_t)j * DF];
        float bv = bbB[(size_t)j * DF];
#pragma unroll
        for (int i = 0; i < 18; i++) {
            float a = att_s[half * 18 + i][j];
            accR[i] += a * rv;
            accB[i] += a * bv;
        }
    }
#pragma unroll
    for (int i = 0; i < 18; i++) {
        size_t row = (size_t)b * N_ + half * 18 + i;
        size_t off = row * DF + d0 + d;
        out[off] = obj[off] + fus[off] + ra[off] * accR[i] + ba[off] * accB[i];
    }
}

extern "C" void kernel_launch(void* const* d_in, const int* in_sizes, int n_in,
                              void* d_out, int out_size) {
    const float* qe    = (const float*)d_in[0];
    const float* obj   = (const float*)d_in[1];
    const float* boxes = (const float*)d_in[2];
    const float* Wq    = (const float*)d_in[3];
    const float* Wo    = (const float*)d_in[4];
    const float* Wfa   = (const float*)d_in[5];
    const float* Wfb   = (const float*)d_in[6];
    const float* Wba   = (const float*)d_in[7];
    const float* Wbb   = (const float*)d_in[8];
    const float* W0    = (const float*)d_in[9];
    const float* b0    = (const float*)d_in[10];
    const float* W1    = (const float*)d_in[11];
    float* out = (float*)d_out;

    float *tmp1, *tmp2, *ra, *rb, *ba, *bb;
    float *pra, *prb, *pba, *pbb, *scp;
    uint32_t *pqe, *pobj, *pfus, *pWq, *pWo, *pWfa, *pWfb, *pW0h;
    cudaGetSymbolAddress((void**)&tmp1, g_tmp1);
    cudaGetSymbolAddress((void**)&tmp2, g_tmp2);
    cudaGetSymbolAddress((void**)&ra,   g_ra);
    cudaGetSymbolAddress((void**)&rb,   g_rb);
    cudaGetSymbolAddress((void**)&ba,   g_ba);
    cudaGetSymbolAddress((void**)&bb,   g_bb);
    cudaGetSymbolAddress((void**)&pqe,  g_pqe);
    cudaGetSymbolAddress((void**)&pobj, g_pobj);
    cudaGetSymbolAddress((void**)&pfus, g_pfus);
    cudaGetSymbolAddress((void**)&pWq,  g_pWq);
    cudaGetSymbolAddress((void**)&pWo,  g_pWo);
    cudaGetSymbolAddress((void**)&pWfa, g_pWfa);
    cudaGetSymbolAddress((void**)&pWfb, g_pWfb);
    cudaGetSymbolAddress((void**)&pW0h, g_pW0h);
    cudaGetSymbolAddress((void**)&pra,  g_pra);
    cudaGetSymbolAddress((void**)&prb,  g_prb);
    cudaGetSymbolAddress((void**)&pba,  g_pba);
    cudaGetSymbolAddress((void**)&pbb,  g_pbb);
    cudaGetSymbolAddress((void**)&scp,  g_scp);

    cudaFuncSetAttribute(gemm_hz, cudaFuncAttributeMaxDynamicSharedMemorySize, G_SMEM);
    cudaFuncSetAttribute(relattn_h4, cudaFuncAttributeMaxDynamicSharedMemorySize, R_SMEM);

    const int nIO = ROWS * DF / 4;           // 1179648

    dim3 gg(DF / 256, ROWS / 128, 2);        // (8, 18, 2)

    boxproj<<<(nIO + 255) / 256, 256>>>(boxes, Wba, Wbb, ba, bb, pba, pbb);   // 1
    packWall<<<dim3(2048, 1, 5), 256>>>(Wq, Wo, Wfa, Wfb, W0,
                                        pWq, pWo, pWfa, pWfb, pW0h);          // 2
    packAh2<<<dim3(4608, 1, 2), 256>>>(qe, obj, pqe, pobj);                   // 3
    gemm_hz<<<gg, 256, G_SMEM>>>(pqe, pWq, tmp1, nullptr,
                                 pobj, pWo, tmp2, nullptr);                   // 4
    fusekh<<<(nIO + 255) / 256, 256>>>(tmp1, tmp2, pfus);                     // 5
    gemm_hz<<<gg, 256, G_SMEM>>>(pfus, pWfa, ra, pra,
                                 pfus, pWfb, rb, prb);                        // 6 (profiled)
    relattn_h4<<<dim3(2, 9, B_), 384, R_SMEM>>>(pra, prb, pba, pbb,
                                                pW0h, b0, W1, scp);           // 7
    ehat_fin2<<<dim3(16, B_), 256>>>(scp, ra, rb, ba, bb, obj, tmp1, out);    // 8
}